// round 13
// baseline (speedup 1.0000x reference)
#include <cuda_runtime.h>
#include <cuda_fp16.h>
#include <stdint.h>
#include <math.h>

// ===========================================================================
// SparseMoeBlock, fp16 mma.sync single-term, R12:
//  - KS=64 stages (half the barriers), NBUF=4, 3 stages in flight
//  - no weight transpose: B kept [K,N], ldmatrix.x4.trans for B fragments
//  - grid ordered m-fastest for B-tile L2 reuse
// ===========================================================================

#define DHID  2048
#define NEXP  16
#define INTER 1408
#define NTOK  8192
#define NASSIGN (NTOK * 2)

#define KS    64
#define AST   72        // A row stride (fp16 elems): 64 + 8 pad -> conflict-free
#define BST1  136       // gemm1 B row stride: 128 + 8 pad
#define BST2  264       // gemm2 B row stride: 256 + 8 pad
#define NBUF  4

// gemm1 stage: A 128x144B, G 64x272B, U 64x272B
#define G1_A 0
#define G1_G 18432
#define G1_U 35840
#define G1_STG 53248
// gemm2 stage: A 128x144B, B 64x528B
#define G2_A 0
#define G2_B 18432
#define G2_STG 52224

#define SMEM1 (NBUF * G1_STG + 128)
#define SMEM2 (NBUF * G2_STG + 128)

// ---------------------------------------------------------------------------
__device__ __forceinline__ uint32_t smem_u32(const void* p) {
    uint32_t a;
    asm("{ .reg .u64 t; cvta.to.shared.u64 t, %1; cvt.u32.u64 %0, t; }" : "=r"(a) : "l"(p));
    return a;
}
#define CP16(dst, src, sz) \
    asm volatile("cp.async.cg.shared.global [%0], [%1], 16, %2;" \
                 :: "r"(dst), "l"(src), "r"(sz))
#define CP_COMMIT() asm volatile("cp.async.commit_group;" ::: "memory")
#define CP_WAIT(n)  asm volatile("cp.async.wait_group %0;" :: "n"(n) : "memory")

#define LDSM4(r0, r1, r2, r3, addr) \
    asm volatile("ldmatrix.sync.aligned.m8n8.x4.shared.b16 {%0,%1,%2,%3}, [%4];" \
                 : "=r"(r0), "=r"(r1), "=r"(r2), "=r"(r3) : "r"(addr))
#define LDSM4T(r0, r1, r2, r3, addr) \
    asm volatile("ldmatrix.sync.aligned.m8n8.x4.trans.shared.b16 {%0,%1,%2,%3}, [%4];" \
                 : "=r"(r0), "=r"(r1), "=r"(r2), "=r"(r3) : "r"(addr))

#define MMA(d, a, b0, b1) \
    asm volatile("mma.sync.aligned.m16n8k16.row.col.f32.f16.f16.f32 " \
                 "{%0,%1,%2,%3}, {%4,%5,%6,%7}, {%8,%9}, {%0,%1,%2,%3};" \
                 : "+f"((d)[0]), "+f"((d)[1]), "+f"((d)[2]), "+f"((d)[3]) \
                 : "r"((a)[0]), "r"((a)[1]), "r"((a)[2]), "r"((a)[3]), \
                   "r"(b0), "r"(b1))

__device__ __forceinline__ uint32_t h2u(__half a, __half b) {
    __half2 t(a, b);
    return *reinterpret_cast<uint32_t*>(&t);
}
__device__ __forceinline__ float silu(float g) {
    return g / (1.0f + expf(-g));
}

// ---------------------------------------------------------------------------
// device scratch
// ---------------------------------------------------------------------------
#define WELEMS (16ull * 2048 * 1408)
__device__ int   g_cnt[NEXP];
__device__ int   g_off[NEXP + 1];
__device__ int   g_tok[NEXP][NTOK];
__device__ int   g_s_e[NTOK][2];
__device__ int   g_s_i[NTOK][2];
__device__ float g_s_w[NTOK][2];
__device__ __half g_x[(size_t)NTOK * DHID];
__device__ __half g_wgH[WELEMS];            // [e][k(2048)][n(1408)]  (native layout)
__device__ __half g_wuH[WELEMS];
__device__ __half g_wdH[WELEMS];            // [e][k(1408)][n(2048)]
__device__ __half g_h[(size_t)NASSIGN * INTER];
__device__ float  g_y[(size_t)NASSIGN * DHID];

// ---------------------------------------------------------------------------
__global__ void zero16_kernel() {
    if (threadIdx.x < NEXP) g_cnt[threadIdx.x] = 0;
}

// ---------------------------------------------------------------------------
__global__ __launch_bounds__(256) void router_kernel(
    const float* __restrict__ x, const float* __restrict__ gw) {
    int gwarp = (blockIdx.x * blockDim.x + threadIdx.x) >> 5;
    int lane  = threadIdx.x & 31;
    if (gwarp >= NTOK) return;
    const float* xr = x + (size_t)gwarp * DHID;

    float acc[NEXP];
#pragma unroll
    for (int e = 0; e < NEXP; ++e) acc[e] = 0.0f;
    for (int d = lane; d < DHID; d += 32) {
        float xv = xr[d];
#pragma unroll
        for (int e = 0; e < NEXP; ++e) acc[e] += xv * gw[e * DHID + d];
    }
#pragma unroll
    for (int e = 0; e < NEXP; ++e)
#pragma unroll
        for (int s = 16; s > 0; s >>= 1)
            acc[e] += __shfl_xor_sync(0xffffffffu, acc[e], s);
    if (lane == 0) {
        float m1 = acc[0]; int a1 = 0;
#pragma unroll
        for (int e = 1; e < NEXP; ++e)
            if (acc[e] > m1) { m1 = acc[e]; a1 = e; }
        float m2 = -INFINITY; int a2 = 0;
#pragma unroll
        for (int e = 0; e < NEXP; ++e)
            if (e != a1 && acc[e] > m2) { m2 = acc[e]; a2 = e; }
        float w1 = 1.0f / (1.0f + expf(m2 - m1));
        float w2 = 1.0f - w1;
        int i1 = atomicAdd(&g_cnt[a1], 1);
        g_tok[a1][i1] = gwarp;
        int i2 = atomicAdd(&g_cnt[a2], 1);
        g_tok[a2][i2] = gwarp;
        g_s_e[gwarp][0] = a1; g_s_i[gwarp][0] = i1; g_s_w[gwarp][0] = w1;
        g_s_e[gwarp][1] = a2; g_s_i[gwarp][1] = i2; g_s_w[gwarp][1] = w2;
    }
}

__global__ void offsets_kernel() {
    if (threadIdx.x == 0) {
        int o = 0;
        for (int e = 0; e < NEXP; ++e) { g_off[e] = o; o += g_cnt[e]; }
        g_off[NEXP] = o;
    }
}

// ---------------------------------------------------------------------------
// streaming fp32 -> fp16 converters (no transpose)
// ---------------------------------------------------------------------------
__global__ __launch_bounds__(256) void convert_x_kernel(const float* __restrict__ x) {
    size_t i = ((size_t)blockIdx.x * blockDim.x + threadIdx.x) * 4;
    if (i >= (size_t)NTOK * DHID) return;
    float4 v = *(const float4*)(x + i);
    *(uint2*)(g_x + i) = make_uint2(
        h2u(__float2half_rn(v.x), __float2half_rn(v.y)),
        h2u(__float2half_rn(v.z), __float2half_rn(v.w)));
}

__global__ __launch_bounds__(256) void convert_w_kernel(
    const float* __restrict__ in, __half* __restrict__ out, size_t n) {
    size_t stride = (size_t)gridDim.x * blockDim.x * 4;
    for (size_t i = ((size_t)blockIdx.x * blockDim.x + threadIdx.x) * 4; i < n; i += stride) {
        float4 v = *(const float4*)(in + i);
        *(uint2*)(out + i) = make_uint2(
            h2u(__float2half_rn(v.x), __float2half_rn(v.y)),
            h2u(__float2half_rn(v.z), __float2half_rn(v.w)));
    }
}

// ---------------------------------------------------------------------------
// GEMM1: CTA 128(m) x 128(n), gate AND up, K=2048, KS=64.
// 8 warps (2m x 4n), warp tile 64x32 per matrix. B via ldmatrix.trans.
// ---------------------------------------------------------------------------
__global__ __launch_bounds__(256, 1) void gemm1_mma(void) {
    int e   = blockIdx.z;
    int cnt = g_cnt[e];
    int m0  = blockIdx.x * 128;          // m fastest -> B-tile L2 reuse
    if (m0 >= cnt) return;
    int n0   = blockIdx.y * 128;
    int base = g_off[e];

    extern __shared__ char dynsm[];
    uint32_t raw = smem_u32(dynsm);
    uint32_t smA = (raw + 127u) & ~127u;

    int tid = threadIdx.x, wid = tid >> 5, lane = tid & 31;

    // producers
    int arow = tid >> 1;                 // A: 128 rows, 2 thr/row, 4 chunks
    int aco  = (tid & 1) * 32;
    bool avalid = (m0 + arow < cnt);
    int atok = avalid ? g_tok[e][m0 + arow] : 0;
    uint32_t asz = avalid ? 16u : 0u;
    const __half* axp = g_x + (size_t)atok * DHID + aco;
    uint32_t adst = arow * (AST * 2) + aco * 2;

    int grow = tid >> 2;                 // G/U: 64 rows, 4 thr/row, 4 chunks
    int gco  = (tid & 3) * 32;
    size_t wrow0 = ((size_t)e * DHID + grow) * INTER + n0 + gco;
    const __half* pg = g_wgH + wrow0;    // advance by KS*INTER per stage
    const __half* pu = g_wuH + wrow0;
    uint32_t gdst = grow * (BST1 * 2) + gco * 2;

    // consumers: warp (2m x 4n), tile 64x32
    int wm = (wid >> 2) * 64;
    int wn = (wid & 3) * 32;
    int arl = lane & 15;
    int acl = (lane >> 4) * 8;
    int bkr = lane & 15;                 // trans: k-row within 16
    int bnc = (lane >> 4) * 8;           // trans: n-col offset {0,8}

    float gacc[4][4][4], uacc[4][4][4];
#pragma unroll
    for (int mb = 0; mb < 4; ++mb)
#pragma unroll
        for (int nb = 0; nb < 4; ++nb)
#pragma unroll
            for (int i = 0; i < 4; ++i) { gacc[mb][nb][i] = 0.f; uacc[mb][nb][i] = 0.f; }

    const int NST = DHID / KS;   // 32

    auto issue = [&](int s) {
        uint32_t st = smA + (s & (NBUF - 1)) * G1_STG;
        int k0 = s * KS;
        const __half* a = axp + k0;
        const __half* g = pg + (size_t)k0 * INTER;
        const __half* u = pu + (size_t)k0 * INTER;
#pragma unroll
        for (int c = 0; c < 4; ++c) {
            CP16(st + G1_A + adst + c * 16, a + c * 8, asz);
            CP16(st + G1_G + gdst + c * 16, g + c * 8, 16u);
            CP16(st + G1_U + gdst + c * 16, u + c * 8, 16u);
        }
    };

    issue(0); CP_COMMIT();
    issue(1); CP_COMMIT();
    issue(2); CP_COMMIT();

    for (int s = 0; s < NST; ++s) {
        CP_WAIT(2);
        __syncthreads();
        uint32_t st = smA + (s & (NBUF - 1)) * G1_STG;
#pragma unroll
        for (int kk = 0; kk < 4; ++kk) {
            int kofs = kk * 16;
            uint32_t ah[4][4];
#pragma unroll
            for (int mb = 0; mb < 4; ++mb) {
                uint32_t ao = ((wm + mb * 16 + arl) * AST + kofs + acl) * 2;
                LDSM4(ah[mb][0], ah[mb][1], ah[mb][2], ah[mb][3], st + G1_A + ao);
            }
            uint32_t bg[2][4], bu[2][4];
#pragma unroll
            for (int p = 0; p < 2; ++p) {
                uint32_t bo = ((kofs + bkr) * BST1 + wn + p * 16 + bnc) * 2;
                LDSM4T(bg[p][0], bg[p][1], bg[p][2], bg[p][3], st + G1_G + bo);
                LDSM4T(bu[p][0], bu[p][1], bu[p][2], bu[p][3], st + G1_U + bo);
            }
#pragma unroll
            for (int mb = 0; mb < 4; ++mb)
#pragma unroll
                for (int nb = 0; nb < 4; ++nb) {
                    int p = nb >> 1, o = (nb & 1) * 2;
                    MMA(gacc[mb][nb], ah[mb], bg[p][o], bg[p][o + 1]);
                    MMA(uacc[mb][nb], ah[mb], bu[p][o], bu[p][o + 1]);
                }
        }
        if (s + 3 < NST) issue(s + 3);
        CP_COMMIT();
    }

    // epilogue: h = silu(g)*u -> fp16
#pragma unroll
    for (int mb = 0; mb < 4; ++mb) {
#pragma unroll
        for (int half = 0; half < 2; ++half) {
            int m = m0 + wm + mb * 16 + (lane >> 2) + half * 8;
            if (m < cnt) {
                __half* hh = g_h + (size_t)(base + m) * INTER + n0;
#pragma unroll
                for (int nb = 0; nb < 4; ++nb) {
                    int c = wn + nb * 8 + (lane & 3) * 2;
                    float g0 = gacc[mb][nb][half * 2],     g1 = gacc[mb][nb][half * 2 + 1];
                    float u0 = uacc[mb][nb][half * 2],     u1 = uacc[mb][nb][half * 2 + 1];
                    float h0 = silu(g0) * u0, h1 = silu(g1) * u1;
                    *(uint32_t*)(hh + c) = h2u(__float2half_rn(h0), __float2half_rn(h1));
                }
            }
        }
    }
}

// ---------------------------------------------------------------------------
// GEMM2: CTA 128(m) x 256(n), K=1408, KS=64. 8 warps (2m x 4n), tile 64x64.
// ---------------------------------------------------------------------------
__global__ __launch_bounds__(256, 1) void gemm2_mma(void) {
    int e   = blockIdx.z;
    int cnt = g_cnt[e];
    int m0  = blockIdx.x * 128;
    if (m0 >= cnt) return;
    int n0   = blockIdx.y * 256;
    int base = g_off[e];

    extern __shared__ char dynsm[];
    uint32_t raw = smem_u32(dynsm);
    uint32_t smA = (raw + 127u) & ~127u;

    int tid = threadIdx.x, wid = tid >> 5, lane = tid & 31;

    // producers
    int arow = tid >> 1;
    int aco  = (tid & 1) * 32;
    bool avalid = (m0 + arow < cnt);
    uint32_t asz = avalid ? 16u : 0u;
    const __half* ahp = g_h + (size_t)(base + (avalid ? m0 + arow : 0)) * INTER + aco;
    uint32_t adst = arow * (AST * 2) + aco * 2;

    int brow = tid >> 2;                 // B: 64 rows, 4 thr/row, 8 chunks
    int bco  = (tid & 3) * 64;
    const __half* bp = g_wdH + ((size_t)e * INTER + brow) * DHID + n0 + bco;
    uint32_t bdst = brow * (BST2 * 2) + bco * 2;

    // consumers: warp (2m x 4n), tile 64x64
    int wm = (wid >> 2) * 64;
    int wn = (wid & 3) * 64;
    int arl = lane & 15, acl = (lane >> 4) * 8;
    int bkr = lane & 15;
    int bnc = (lane >> 4) * 8;

    float acc[4][8][4];
#pragma unroll
    for (int mb = 0; mb < 4; ++mb)
#pragma unroll
        for (int nb = 0; nb < 8; ++nb)
#pragma unroll
            for (int i = 0; i < 4; ++i) acc[mb][nb][i] = 0.f;

    const int NST = INTER / KS;  // 22

    auto issue = [&](int s) {
        uint32_t st = smA + (s & (NBUF - 1)) * G2_STG;
        int k0 = s * KS;
        const __half* a = ahp + k0;
        const __half* b = bp + (size_t)k0 * DHID;
#pragma unroll
        for (int c = 0; c < 4; ++c)
            CP16(st + G2_A + adst + c * 16, a + c * 8, asz);
#pragma unroll
        for (int c = 0; c < 8; ++c)
            CP16(st + G2_B + bdst + c * 16, b + c * 8, 16u);
    };

    issue(0); CP_COMMIT();
    issue(1); CP_COMMIT();
    issue(2); CP_COMMIT();

    for (int s = 0; s < NST; ++s) {
        CP_WAIT(2);
        __syncthreads();
        uint32_t st = smA + (s & (NBUF - 1)) * G2_STG;
#pragma unroll
        for (int kk = 0; kk < 4; ++kk) {
            int kofs = kk * 16;
            uint32_t ah[4][4];
#pragma unroll
            for (int mb = 0; mb < 4; ++mb) {
                uint32_t ao = ((wm + mb * 16 + arl) * AST + kofs + acl) * 2;
                LDSM4(ah[mb][0], ah[mb][1], ah[mb][2], ah[mb][3], st + G2_A + ao);
            }
            uint32_t bh[4][4];
#pragma unroll
            for (int p = 0; p < 4; ++p) {
                uint32_t bo = ((kofs + bkr) * BST2 + wn + p * 16 + bnc) * 2;
                LDSM4T(bh[p][0], bh[p][1], bh[p][2], bh[p][3], st + G2_B + bo);
            }
#pragma unroll
            for (int mb = 0; mb < 4; ++mb)
#pragma unroll
                for (int nb = 0; nb < 8; ++nb) {
                    int p = nb >> 1, o = (nb & 1) * 2;
                    MMA(acc[mb][nb], ah[mb], bh[p][o], bh[p][o + 1]);
                }
        }
        if (s + 3 < NST) issue(s + 3);
        CP_COMMIT();
    }

    // epilogue: plain stores to g_y
#pragma unroll
    for (int mb = 0; mb < 4; ++mb) {
#pragma unroll
        for (int half = 0; half < 2; ++half) {
            int m = m0 + wm + mb * 16 + (lane >> 2) + half * 8;
            if (m < cnt) {
                float* yrow = g_y + (size_t)(base + m) * DHID + n0;
#pragma unroll
                for (int nb = 0; nb < 8; ++nb) {
                    int c = wn + nb * 8 + (lane & 3) * 2;
                    float2 v = make_float2(acc[mb][nb][half * 2], acc[mb][nb][half * 2 + 1]);
                    *(float2*)(yrow + c) = v;
                }
            }
        }
    }
}

// ---------------------------------------------------------------------------
// Combine: out[t] = w0 * y[slot(t,0)] + w1 * y[slot(t,1)]
// ---------------------------------------------------------------------------
__global__ __launch_bounds__(256) void combine_kernel(float* __restrict__ out) {
    int t = blockIdx.x;
    int e0 = g_s_e[t][0], e1 = g_s_e[t][1];
    size_t s0 = (size_t)(g_off[e0] + g_s_i[t][0]) * DHID;
    size_t s1 = (size_t)(g_off[e1] + g_s_i[t][1]) * DHID;
    float w0 = g_s_w[t][0], w1 = g_s_w[t][1];
    size_t ob = (size_t)t * DHID;
#pragma unroll
    for (int r = 0; r < 2; ++r) {
        int c = (threadIdx.x + r * 256) * 4;
        float4 a = *(const float4*)(g_y + s0 + c);
        float4 b = *(const float4*)(g_y + s1 + c);
        float4 o;
        o.x = w0 * a.x + w1 * b.x;
        o.y = w0 * a.y + w1 * b.y;
        o.z = w0 * a.z + w1 * b.z;
        o.w = w0 * a.w + w1 * b.w;
        *(float4*)(out + ob + c) = o;
    }
}

// ---------------------------------------------------------------------------
extern "C" void kernel_launch(void* const* d_in, const int* in_sizes, int n_in,
                              void* d_out, int out_size) {
    const float* x  = (const float*)d_in[0];
    const float* gw = (const float*)d_in[1];
    const float* wg = (const float*)d_in[2];
    const float* wu = (const float*)d_in[3];
    const float* wd = (const float*)d_in[4];
    float* out = (float*)d_out;

    static __half* wg_p = nullptr;   // resolve device-symbol addresses once
    __half *d_wg, *d_wu, *d_wd;
    (void)wg_p;
    cudaGetSymbolAddress((void**)&d_wg, g_wgH);
    cudaGetSymbolAddress((void**)&d_wu, g_wuH);
    cudaGetSymbolAddress((void**)&d_wd, g_wdH);

    cudaFuncSetAttribute(gemm1_mma, cudaFuncAttributeMaxDynamicSharedMemorySize, SMEM1);
    cudaFuncSetAttribute(gemm2_mma, cudaFuncAttributeMaxDynamicSharedMemorySize, SMEM2);

    zero16_kernel<<<1, 32>>>();
    router_kernel<<<NTOK / 8, 256>>>(x, gw);
    offsets_kernel<<<1, 32>>>();
    convert_x_kernel<<<(NTOK * DHID / 4 + 255) / 256, 256>>>(x);
    convert_w_kernel<<<4096, 256>>>(wg, d_wg, WELEMS);
    convert_w_kernel<<<4096, 256>>>(wu, d_wu, WELEMS);
    convert_w_kernel<<<4096, 256>>>(wd, d_wd, WELEMS);
    gemm1_mma<<<dim3(NTOK / 128, INTER / 128, NEXP), 256, SMEM1>>>();
    gemm2_mma<<<dim3(NTOK / 128, DHID / 256, NEXP), 256, SMEM2>>>();
    combine_kernel<<<NTOK, 256>>>(out);
}

// round 15
// speedup vs baseline: 1.1341x; 1.1341x over previous
#include <cuda_runtime.h>
#include <cuda_fp16.h>
#include <stdint.h>
#include <math.h>

// ===========================================================================
// SparseMoeBlock, fp16 mma.sync single-term. R14 = R11 structure (KS=32,
// NBUF=6, transposed [N,K] weights, non-trans ldmatrix) but 512 threads /
// 16 warps per CTA (4 warps/SMSP) to hide shared-memory latency.
// ===========================================================================

#define DHID  2048
#define NEXP  16
#define INTER 1408
#define NTOK  8192
#define NASSIGN (NTOK * 2)

#define KS       32
#define ASTRIDE  40            // smem row stride in fp16 (80B)
#define NBUF     6

// gemm1 stage: A (128x80B), G (128x80B), U (128x80B)
#define G1_A  0
#define G1_G  10240
#define G1_U  20480
// gemm2 stage: A (128x80B), B (256x80B)
#define G2_A  0
#define G2_B  10240
#define STAGE_B 30720

#define SMEM_DYN (NBUF * STAGE_B + 128)

// ---------------------------------------------------------------------------
__device__ __forceinline__ uint32_t smem_u32(const void* p) {
    uint32_t a;
    asm("{ .reg .u64 t; cvta.to.shared.u64 t, %1; cvt.u32.u64 %0, t; }" : "=r"(a) : "l"(p));
    return a;
}
#define CP16(dst, src, sz) \
    asm volatile("cp.async.cg.shared.global [%0], [%1], 16, %2;" \
                 :: "r"(dst), "l"(src), "r"(sz))
#define CP_COMMIT() asm volatile("cp.async.commit_group;" ::: "memory")
#define CP_WAIT(n)  asm volatile("cp.async.wait_group %0;" :: "n"(n) : "memory")

#define LDSM4(r0, r1, r2, r3, addr) \
    asm volatile("ldmatrix.sync.aligned.m8n8.x4.shared.b16 {%0,%1,%2,%3}, [%4];" \
                 : "=r"(r0), "=r"(r1), "=r"(r2), "=r"(r3) : "r"(addr))

#define MMA(d, a, b0, b1) \
    asm volatile("mma.sync.aligned.m16n8k16.row.col.f32.f16.f16.f32 " \
                 "{%0,%1,%2,%3}, {%4,%5,%6,%7}, {%8,%9}, {%0,%1,%2,%3};" \
                 : "+f"((d)[0]), "+f"((d)[1]), "+f"((d)[2]), "+f"((d)[3]) \
                 : "r"((a)[0]), "r"((a)[1]), "r"((a)[2]), "r"((a)[3]), \
                   "r"(b0), "r"(b1))

__device__ __forceinline__ uint32_t h2u(__half a, __half b) {
    __half2 t(a, b);
    return *reinterpret_cast<uint32_t*>(&t);
}
__device__ __forceinline__ float silu(float g) {
    return g / (1.0f + expf(-g));
}

// ---------------------------------------------------------------------------
// device scratch
// ---------------------------------------------------------------------------
#define WELEMS (16ull * 2048 * 1408)
__device__ int   g_cnt[NEXP];
__device__ int   g_off[NEXP + 1];
__device__ int   g_tok[NEXP][NTOK];
__device__ int   g_s_e[NTOK][2];
__device__ int   g_s_i[NTOK][2];
__device__ float g_s_w[NTOK][2];
__device__ __half g_x[(size_t)NTOK * DHID];
__device__ __half g_wgT[WELEMS];            // [e][n(1408)][k(2048)]
__device__ __half g_wuT[WELEMS];
__device__ __half g_wdT[WELEMS];            // [e][n(2048)][k(1408)]
__device__ __half g_h[(size_t)NASSIGN * INTER];
__device__ float  g_y[(size_t)NASSIGN * DHID];

// ---------------------------------------------------------------------------
__global__ void zero16_kernel() {
    if (threadIdx.x < NEXP) g_cnt[threadIdx.x] = 0;
}

// ---------------------------------------------------------------------------
__global__ __launch_bounds__(256) void router_kernel(
    const float* __restrict__ x, const float* __restrict__ gw) {
    int gwarp = (blockIdx.x * blockDim.x + threadIdx.x) >> 5;
    int lane  = threadIdx.x & 31;
    if (gwarp >= NTOK) return;
    const float* xr = x + (size_t)gwarp * DHID;

    float acc[NEXP];
#pragma unroll
    for (int e = 0; e < NEXP; ++e) acc[e] = 0.0f;
    for (int d = lane; d < DHID; d += 32) {
        float xv = xr[d];
#pragma unroll
        for (int e = 0; e < NEXP; ++e) acc[e] += xv * gw[e * DHID + d];
    }
#pragma unroll
    for (int e = 0; e < NEXP; ++e)
#pragma unroll
        for (int s = 16; s > 0; s >>= 1)
            acc[e] += __shfl_xor_sync(0xffffffffu, acc[e], s);
    if (lane == 0) {
        float m1 = acc[0]; int a1 = 0;
#pragma unroll
        for (int e = 1; e < NEXP; ++e)
            if (acc[e] > m1) { m1 = acc[e]; a1 = e; }
        float m2 = -INFINITY; int a2 = 0;
#pragma unroll
        for (int e = 0; e < NEXP; ++e)
            if (e != a1 && acc[e] > m2) { m2 = acc[e]; a2 = e; }
        float w1 = 1.0f / (1.0f + expf(m2 - m1));
        float w2 = 1.0f - w1;
        int i1 = atomicAdd(&g_cnt[a1], 1);
        g_tok[a1][i1] = gwarp;
        int i2 = atomicAdd(&g_cnt[a2], 1);
        g_tok[a2][i2] = gwarp;
        g_s_e[gwarp][0] = a1; g_s_i[gwarp][0] = i1; g_s_w[gwarp][0] = w1;
        g_s_e[gwarp][1] = a2; g_s_i[gwarp][1] = i2; g_s_w[gwarp][1] = w2;
    }
}

__global__ void offsets_kernel() {
    if (threadIdx.x == 0) {
        int o = 0;
        for (int e = 0; e < NEXP; ++e) { g_off[e] = o; o += g_cnt[e]; }
        g_off[NEXP] = o;
    }
}

// ---------------------------------------------------------------------------
__global__ __launch_bounds__(256) void convert_x_kernel(const float* __restrict__ x) {
    size_t i = ((size_t)blockIdx.x * blockDim.x + threadIdx.x) * 4;
    if (i >= (size_t)NTOK * DHID) return;
    float4 v = *(const float4*)(x + i);
    *(uint2*)(g_x + i) = make_uint2(
        h2u(__float2half_rn(v.x), __float2half_rn(v.y)),
        h2u(__float2half_rn(v.z), __float2half_rn(v.w)));
}

// ---------------------------------------------------------------------------
__global__ __launch_bounds__(256) void transpose_h_kernel(
    const float* __restrict__ in, int which, int K, int N) {
    __shared__ float t[32][33];
    int e = blockIdx.z;
    const float* ine = in + (size_t)e * K * N;
    __half* oh = (which == 0) ? g_wgT : (which == 1) ? g_wuT : g_wdT;
    size_t ob = (size_t)e * K * N;
    int n0 = blockIdx.x * 32, k0 = blockIdx.y * 32;
    int tx = threadIdx.x, ty = threadIdx.y;    // 32 x 8
#pragma unroll
    for (int j = 0; j < 4; ++j)
        t[ty + j * 8][tx] = ine[(size_t)(k0 + ty + j * 8) * N + n0 + tx];
    __syncthreads();
#pragma unroll
    for (int j = 0; j < 4; ++j) {
        int n = n0 + ty + j * 8, k = k0 + tx;
        oh[ob + (size_t)n * K + k] = __float2half_rn(t[tx][ty + j * 8]);
    }
}

// ---------------------------------------------------------------------------
// GEMM1: CTA 128(m) x 128(n), gate AND up, K=2048, KS=32. 16 warps (4m x 4n),
// warp tile 32x32 per matrix. Single-term fp16 mma. 6-deep pipe.
// ---------------------------------------------------------------------------
__global__ __launch_bounds__(512, 1) void gemm1_mma(void) {
    int e   = blockIdx.z;
    int cnt = g_cnt[e];
    int m0  = blockIdx.y * 128;
    if (m0 >= cnt) return;
    int n0   = blockIdx.x * 128;
    int base = g_off[e];

    extern __shared__ char dynsm[];
    uint32_t raw = smem_u32(dynsm);
    uint32_t smA = (raw + 127u) & ~127u;

    int tid = threadIdx.x, wid = tid >> 5, lane = tid & 31;

    // producers: 512 threads, each matrix 128 rows x 4 chunks = 1 chunk/thread
    int arow = tid >> 2;
    int aco  = (tid & 3) * 8;              // elem offset
    bool avalid = (m0 + arow < cnt);
    int atok = avalid ? g_tok[e][m0 + arow] : 0;
    uint32_t asz = avalid ? 16u : 0u;
    const __half* axp = g_x + (size_t)atok * DHID + aco;
    size_t wbase = ((size_t)e * INTER + n0 + arow) * DHID + aco;
    const __half* bg_src = g_wgT + wbase;
    const __half* bu_src = g_wuT + wbase;
    uint32_t adst = arow * 80 + aco * 2;

    // consumers: warp (4m x 4n), tile 32x32
    int wm = (wid >> 2) * 32;
    int wn = (wid & 3) * 32;
    int arl = lane & 15;
    int acl = (lane >> 4) * 8;
    int bnl = (lane & 7) + ((lane >> 4) << 3);
    int bkl = ((lane >> 3) & 1) * 8;

    float gacc[2][4][4], uacc[2][4][4];
#pragma unroll
    for (int mb = 0; mb < 2; ++mb)
#pragma unroll
        for (int nb = 0; nb < 4; ++nb)
#pragma unroll
            for (int i = 0; i < 4; ++i) { gacc[mb][nb][i] = 0.f; uacc[mb][nb][i] = 0.f; }

    const int NST = DHID / KS;   // 64

    auto issue = [&](int s) {
        uint32_t st = smA + (s % NBUF) * STAGE_B;
        int k0 = s * KS;
        CP16(st + G1_A + adst, axp + k0, asz);
        CP16(st + G1_G + adst, bg_src + k0, 16u);
        CP16(st + G1_U + adst, bu_src + k0, 16u);
    };

    issue(0); CP_COMMIT();
    issue(1); CP_COMMIT();
    issue(2); CP_COMMIT();
    issue(3); CP_COMMIT();
    issue(4); CP_COMMIT();

    for (int s = 0; s < NST; ++s) {
        CP_WAIT(4);
        __syncthreads();
        uint32_t st = smA + (s % NBUF) * STAGE_B;
#pragma unroll
        for (int kk = 0; kk < 2; ++kk) {
            int kofs = kk * 16;
            uint32_t ah[2][4];
#pragma unroll
            for (int mb = 0; mb < 2; ++mb) {
                uint32_t ao = ((wm + mb * 16 + arl) * ASTRIDE + kofs + acl) * 2;
                LDSM4(ah[mb][0], ah[mb][1], ah[mb][2], ah[mb][3], st + G1_A + ao);
            }
            uint32_t bg[2][4], bu[2][4];
#pragma unroll
            for (int p = 0; p < 2; ++p) {
                uint32_t bo = ((wn + p * 16 + bnl) * ASTRIDE + kofs + bkl) * 2;
                LDSM4(bg[p][0], bg[p][1], bg[p][2], bg[p][3], st + G1_G + bo);
                LDSM4(bu[p][0], bu[p][1], bu[p][2], bu[p][3], st + G1_U + bo);
            }
#pragma unroll
            for (int mb = 0; mb < 2; ++mb)
#pragma unroll
                for (int nb = 0; nb < 4; ++nb) {
                    int p = nb >> 1, o = (nb & 1) * 2;
                    MMA(gacc[mb][nb], ah[mb], bg[p][o], bg[p][o + 1]);
                    MMA(uacc[mb][nb], ah[mb], bu[p][o], bu[p][o + 1]);
                }
        }
        if (s + 5 < NST) issue(s + 5);
        CP_COMMIT();
    }

    // epilogue: h = silu(g)*u -> fp16
#pragma unroll
    for (int mb = 0; mb < 2; ++mb) {
#pragma unroll
        for (int half = 0; half < 2; ++half) {
            int m = m0 + wm + mb * 16 + (lane >> 2) + half * 8;
            if (m < cnt) {
                __half* hh = g_h + (size_t)(base + m) * INTER + n0;
#pragma unroll
                for (int nb = 0; nb < 4; ++nb) {
                    int c = wn + nb * 8 + (lane & 3) * 2;
                    float g0 = gacc[mb][nb][half * 2],     g1 = gacc[mb][nb][half * 2 + 1];
                    float u0 = uacc[mb][nb][half * 2],     u1 = uacc[mb][nb][half * 2 + 1];
                    float h0 = silu(g0) * u0, h1 = silu(g1) * u1;
                    *(uint32_t*)(hh + c) = h2u(__float2half_rn(h0), __float2half_rn(h1));
                }
            }
        }
    }
}

// ---------------------------------------------------------------------------
// GEMM2: CTA 128(m) x 256(n), K=1408, KS=32. 16 warps (2m x 8n),
// warp tile 64x32. Plain stores to g_y.
// ---------------------------------------------------------------------------
__global__ __launch_bounds__(512, 1) void gemm2_mma(void) {
    int e   = blockIdx.z;
    int cnt = g_cnt[e];
    int m0  = blockIdx.y * 128;
    if (m0 >= cnt) return;
    int n0   = blockIdx.x * 256;
    int base = g_off[e];

    extern __shared__ char dynsm[];
    uint32_t raw = smem_u32(dynsm);
    uint32_t smA = (raw + 127u) & ~127u;

    int tid = threadIdx.x, wid = tid >> 5, lane = tid & 31;

    // producers: A 128 rows x 4 chunks = 1/thread; B 256 rows x 4 chunks = 2/thread
    int arow = tid >> 2;
    int aco  = (tid & 3) * 8;
    bool avalid = (m0 + arow < cnt);
    uint32_t asz = avalid ? 16u : 0u;
    const __half* ahp = g_h + (size_t)(base + (avalid ? m0 + arow : 0)) * INTER + aco;
    uint32_t adst = arow * 80 + aco * 2;

    int brow = tid >> 1;
    int bco  = (tid & 1) * 16;             // 2 chunks of 8 elems
    const __half* bp = g_wdT + ((size_t)e * DHID + n0 + brow) * INTER + bco;
    uint32_t bdst = brow * 80 + bco * 2;

    // consumers: warp (2m x 8n), tile 64x32
    int wm = (wid >> 3) * 64;
    int wn = (wid & 7) * 32;
    int arl = lane & 15, acl = (lane >> 4) * 8;
    int bnl = (lane & 7) + ((lane >> 4) << 3);
    int bkl = ((lane >> 3) & 1) * 8;

    float acc[4][4][4];
#pragma unroll
    for (int mb = 0; mb < 4; ++mb)
#pragma unroll
        for (int nb = 0; nb < 4; ++nb)
#pragma unroll
            for (int i = 0; i < 4; ++i) acc[mb][nb][i] = 0.f;

    const int NST = INTER / KS;  // 44

    auto issue = [&](int s) {
        uint32_t st = smA + (s % NBUF) * STAGE_B;
        int k0 = s * KS;
        CP16(st + G2_A + adst, ahp + k0, asz);
        CP16(st + G2_B + bdst,      bp + k0,     16u);
        CP16(st + G2_B + bdst + 16, bp + k0 + 8, 16u);
    };

    issue(0); CP_COMMIT();
    issue(1); CP_COMMIT();
    issue(2); CP_COMMIT();
    issue(3); CP_COMMIT();
    issue(4); CP_COMMIT();

    for (int s = 0; s < NST; ++s) {
        CP_WAIT(4);
        __syncthreads();
        uint32_t st = smA + (s % NBUF) * STAGE_B;
#pragma unroll
        for (int kk = 0; kk < 2; ++kk) {
            int kofs = kk * 16;
            uint32_t ah[4][4];
#pragma unroll
            for (int mb = 0; mb < 4; ++mb) {
                uint32_t ao = ((wm + mb * 16 + arl) * ASTRIDE + kofs + acl) * 2;
                LDSM4(ah[mb][0], ah[mb][1], ah[mb][2], ah[mb][3], st + G2_A + ao);
            }
            uint32_t bh[2][4];
#pragma unroll
            for (int p = 0; p < 2; ++p) {
                uint32_t bo = ((wn + p * 16 + bnl) * ASTRIDE + kofs + bkl) * 2;
                LDSM4(bh[p][0], bh[p][1], bh[p][2], bh[p][3], st + G2_B + bo);
            }
#pragma unroll
            for (int mb = 0; mb < 4; ++mb)
#pragma unroll
                for (int nb = 0; nb < 4; ++nb) {
                    int p = nb >> 1, o = (nb & 1) * 2;
                    MMA(acc[mb][nb], ah[mb], bh[p][o], bh[p][o + 1]);
                }
        }
        if (s + 5 < NST) issue(s + 5);
        CP_COMMIT();
    }

    // epilogue: plain stores to g_y
#pragma unroll
    for (int mb = 0; mb < 4; ++mb) {
#pragma unroll
        for (int half = 0; half < 2; ++half) {
            int m = m0 + wm + mb * 16 + (lane >> 2) + half * 8;
            if (m < cnt) {
                float* yrow = g_y + (size_t)(base + m) * DHID + n0;
#pragma unroll
                for (int nb = 0; nb < 4; ++nb) {
                    int c = wn + nb * 8 + (lane & 3) * 2;
                    float2 v = make_float2(acc[mb][nb][half * 2], acc[mb][nb][half * 2 + 1]);
                    *(float2*)(yrow + c) = v;
                }
            }
        }
    }
}

// ---------------------------------------------------------------------------
// Combine: out[t] = w0 * y[slot(t,0)] + w1 * y[slot(t,1)]
// ---------------------------------------------------------------------------
__global__ __launch_bounds__(256) void combine_kernel(float* __restrict__ out) {
    int t = blockIdx.x;
    int e0 = g_s_e[t][0], e1 = g_s_e[t][1];
    size_t s0 = (size_t)(g_off[e0] + g_s_i[t][0]) * DHID;
    size_t s1 = (size_t)(g_off[e1] + g_s_i[t][1]) * DHID;
    float w0 = g_s_w[t][0], w1 = g_s_w[t][1];
    size_t ob = (size_t)t * DHID;
#pragma unroll
    for (int r = 0; r < 2; ++r) {
        int c = (threadIdx.x + r * 256) * 4;
        float4 a = *(const float4*)(g_y + s0 + c);
        float4 b = *(const float4*)(g_y + s1 + c);
        float4 o;
        o.x = w0 * a.x + w1 * b.x;
        o.y = w0 * a.y + w1 * b.y;
        o.z = w0 * a.z + w1 * b.z;
        o.w = w0 * a.w + w1 * b.w;
        *(float4*)(out + ob + c) = o;
    }
}

// ---------------------------------------------------------------------------
extern "C" void kernel_launch(void* const* d_in, const int* in_sizes, int n_in,
                              void* d_out, int out_size) {
    const float* x  = (const float*)d_in[0];
    const float* gw = (const float*)d_in[1];
    const float* wg = (const float*)d_in[2];
    const float* wu = (const float*)d_in[3];
    const float* wd = (const float*)d_in[4];
    float* out = (float*)d_out;

    cudaFuncSetAttribute(gemm1_mma, cudaFuncAttributeMaxDynamicSharedMemorySize, SMEM_DYN);
    cudaFuncSetAttribute(gemm2_mma, cudaFuncAttributeMaxDynamicSharedMemorySize, SMEM_DYN);

    zero16_kernel<<<1, 32>>>();
    router_kernel<<<NTOK / 8, 256>>>(x, gw);
    offsets_kernel<<<1, 32>>>();
    convert_x_kernel<<<(NTOK * DHID / 4 + 255) / 256, 256>>>(x);
    transpose_h_kernel<<<dim3(INTER / 32, DHID / 32, NEXP), dim3(32, 8)>>>(wg, 0, DHID, INTER);
    transpose_h_kernel<<<dim3(INTER / 32, DHID / 32, NEXP), dim3(32, 8)>>>(wu, 1, DHID, INTER);
    transpose_h_kernel<<<dim3(DHID / 32, INTER / 32, NEXP), dim3(32, 8)>>>(wd, 2, INTER, DHID);
    gemm1_mma<<<dim3(INTER / 128, NTOK / 128, NEXP), 512, SMEM_DYN>>>();
    gemm2_mma<<<dim3(DHID / 256, NTOK / 128, NEXP), 512, SMEM_DYN>>>();
    combine_kernel<<<NTOK, 256>>>(out);
}

// round 16
// speedup vs baseline: 1.1647x; 1.0270x over previous
#include <cuda_runtime.h>
#include <cuda_fp16.h>
#include <stdint.h>
#include <math.h>

// ===========================================================================
// SparseMoeBlock, fp16 mma.sync single-term. R16 = R14 (512 thr, 16 warps,
// 4/SMSP) with KS=64 stages (half the barriers), NBUF=4, fp16 g_y.
// ===========================================================================

#define DHID  2048
#define NEXP  16
#define INTER 1408
#define NTOK  8192
#define NASSIGN (NTOK * 2)

#define KS    64
#define AST   72               // smem row stride (fp16 elems) = 144B; 144%128=16 -> conflict-free
#define NBUF  4

// gemm1 stage: A (128x144B), G (128x144B), U (128x144B)
#define G1_A  0
#define G1_G  18432
#define G1_U  36864
// gemm2 stage: A (128x144B), B (256x144B)
#define G2_A  0
#define G2_B  18432
#define STAGE_B 55296

#define SMEM_DYN (NBUF * STAGE_B + 128)

// ---------------------------------------------------------------------------
__device__ __forceinline__ uint32_t smem_u32(const void* p) {
    uint32_t a;
    asm("{ .reg .u64 t; cvta.to.shared.u64 t, %1; cvt.u32.u64 %0, t; }" : "=r"(a) : "l"(p));
    return a;
}
#define CP16(dst, src, sz) \
    asm volatile("cp.async.cg.shared.global [%0], [%1], 16, %2;" \
                 :: "r"(dst), "l"(src), "r"(sz))
#define CP_COMMIT() asm volatile("cp.async.commit_group;" ::: "memory")
#define CP_WAIT(n)  asm volatile("cp.async.wait_group %0;" :: "n"(n) : "memory")

#define LDSM4(r0, r1, r2, r3, addr) \
    asm volatile("ldmatrix.sync.aligned.m8n8.x4.shared.b16 {%0,%1,%2,%3}, [%4];" \
                 : "=r"(r0), "=r"(r1), "=r"(r2), "=r"(r3) : "r"(addr))

#define MMA(d, a, b0, b1) \
    asm volatile("mma.sync.aligned.m16n8k16.row.col.f32.f16.f16.f32 " \
                 "{%0,%1,%2,%3}, {%4,%5,%6,%7}, {%8,%9}, {%0,%1,%2,%3};" \
                 : "+f"((d)[0]), "+f"((d)[1]), "+f"((d)[2]), "+f"((d)[3]) \
                 : "r"((a)[0]), "r"((a)[1]), "r"((a)[2]), "r"((a)[3]), \
                   "r"(b0), "r"(b1))

__device__ __forceinline__ uint32_t h2u(__half a, __half b) {
    __half2 t(a, b);
    return *reinterpret_cast<uint32_t*>(&t);
}
__device__ __forceinline__ float silu(float g) {
    return g / (1.0f + expf(-g));
}

// ---------------------------------------------------------------------------
// device scratch
// ---------------------------------------------------------------------------
#define WELEMS (16ull * 2048 * 1408)
__device__ int   g_cnt[NEXP];
__device__ int   g_off[NEXP + 1];
__device__ int   g_tok[NEXP][NTOK];
__device__ int   g_s_e[NTOK][2];
__device__ int   g_s_i[NTOK][2];
__device__ float g_s_w[NTOK][2];
__device__ __half g_x[(size_t)NTOK * DHID];
__device__ __half g_wgT[WELEMS];            // [e][n(1408)][k(2048)]
__device__ __half g_wuT[WELEMS];
__device__ __half g_wdT[WELEMS];            // [e][n(2048)][k(1408)]
__device__ __half g_h[(size_t)NASSIGN * INTER];
__device__ __half g_y[(size_t)NASSIGN * DHID];   // fp16 per-assignment outputs

// ---------------------------------------------------------------------------
__global__ void zero16_kernel() {
    if (threadIdx.x < NEXP) g_cnt[threadIdx.x] = 0;
}

// ---------------------------------------------------------------------------
__global__ __launch_bounds__(256) void router_kernel(
    const float* __restrict__ x, const float* __restrict__ gw) {
    int gwarp = (blockIdx.x * blockDim.x + threadIdx.x) >> 5;
    int lane  = threadIdx.x & 31;
    if (gwarp >= NTOK) return;
    const float* xr = x + (size_t)gwarp * DHID;

    float acc[NEXP];
#pragma unroll
    for (int e = 0; e < NEXP; ++e) acc[e] = 0.0f;
    for (int d = lane; d < DHID; d += 32) {
        float xv = xr[d];
#pragma unroll
        for (int e = 0; e < NEXP; ++e) acc[e] += xv * gw[e * DHID + d];
    }
#pragma unroll
    for (int e = 0; e < NEXP; ++e)
#pragma unroll
        for (int s = 16; s > 0; s >>= 1)
            acc[e] += __shfl_xor_sync(0xffffffffu, acc[e], s);
    if (lane == 0) {
        float m1 = acc[0]; int a1 = 0;
#pragma unroll
        for (int e = 1; e < NEXP; ++e)
            if (acc[e] > m1) { m1 = acc[e]; a1 = e; }
        float m2 = -INFINITY; int a2 = 0;
#pragma unroll
        for (int e = 0; e < NEXP; ++e)
            if (e != a1 && acc[e] > m2) { m2 = acc[e]; a2 = e; }
        float w1 = 1.0f / (1.0f + expf(m2 - m1));
        float w2 = 1.0f - w1;
        int i1 = atomicAdd(&g_cnt[a1], 1);
        g_tok[a1][i1] = gwarp;
        int i2 = atomicAdd(&g_cnt[a2], 1);
        g_tok[a2][i2] = gwarp;
        g_s_e[gwarp][0] = a1; g_s_i[gwarp][0] = i1; g_s_w[gwarp][0] = w1;
        g_s_e[gwarp][1] = a2; g_s_i[gwarp][1] = i2; g_s_w[gwarp][1] = w2;
    }
}

__global__ void offsets_kernel() {
    if (threadIdx.x == 0) {
        int o = 0;
        for (int e = 0; e < NEXP; ++e) { g_off[e] = o; o += g_cnt[e]; }
        g_off[NEXP] = o;
    }
}

// ---------------------------------------------------------------------------
__global__ __launch_bounds__(256) void convert_x_kernel(const float* __restrict__ x) {
    size_t i = ((size_t)blockIdx.x * blockDim.x + threadIdx.x) * 4;
    if (i >= (size_t)NTOK * DHID) return;
    float4 v = *(const float4*)(x + i);
    *(uint2*)(g_x + i) = make_uint2(
        h2u(__float2half_rn(v.x), __float2half_rn(v.y)),
        h2u(__float2half_rn(v.z), __float2half_rn(v.w)));
}

// ---------------------------------------------------------------------------
__global__ __launch_bounds__(256) void transpose_h_kernel(
    const float* __restrict__ in, int which, int K, int N) {
    __shared__ float t[32][33];
    int e = blockIdx.z;
    const float* ine = in + (size_t)e * K * N;
    __half* oh = (which == 0) ? g_wgT : (which == 1) ? g_wuT : g_wdT;
    size_t ob = (size_t)e * K * N;
    int n0 = blockIdx.x * 32, k0 = blockIdx.y * 32;
    int tx = threadIdx.x, ty = threadIdx.y;    // 32 x 8
#pragma unroll
    for (int j = 0; j < 4; ++j)
        t[ty + j * 8][tx] = ine[(size_t)(k0 + ty + j * 8) * N + n0 + tx];
    __syncthreads();
#pragma unroll
    for (int j = 0; j < 4; ++j) {
        int n = n0 + ty + j * 8, k = k0 + tx;
        oh[ob + (size_t)n * K + k] = __float2half_rn(t[tx][ty + j * 8]);
    }
}

// ---------------------------------------------------------------------------
// GEMM1: CTA 128(m) x 128(n), gate AND up, K=2048, KS=64. 16 warps (4m x 4n),
// warp tile 32x32 per matrix.
// ---------------------------------------------------------------------------
__global__ __launch_bounds__(512, 1) void gemm1_mma(void) {
    int e   = blockIdx.z;
    int cnt = g_cnt[e];
    int m0  = blockIdx.y * 128;
    if (m0 >= cnt) return;
    int n0   = blockIdx.x * 128;
    int base = g_off[e];

    extern __shared__ char dynsm[];
    uint32_t raw = smem_u32(dynsm);
    uint32_t smA = (raw + 127u) & ~127u;

    int tid = threadIdx.x, wid = tid >> 5, lane = tid & 31;

    // producers: each matrix 128 rows x 128B; 4 thr/row, 2 x 16B chunks each
    int arow = tid >> 2;
    int aco  = (tid & 3) * 16;             // elem offset within 64
    bool avalid = (m0 + arow < cnt);
    int atok = avalid ? g_tok[e][m0 + arow] : 0;
    uint32_t asz = avalid ? 16u : 0u;
    const __half* axp = g_x + (size_t)atok * DHID + aco;
    size_t wbase = ((size_t)e * INTER + n0 + arow) * DHID + aco;
    const __half* bg_src = g_wgT + wbase;
    const __half* bu_src = g_wuT + wbase;
    uint32_t adst = arow * (AST * 2) + aco * 2;

    // consumers: warp (4m x 4n), tile 32x32
    int wm = (wid >> 2) * 32;
    int wn = (wid & 3) * 32;
    int arl = lane & 15;
    int acl = (lane >> 4) * 8;
    int bnl = (lane & 7) + ((lane >> 4) << 3);
    int bkl = ((lane >> 3) & 1) * 8;

    float gacc[2][4][4], uacc[2][4][4];
#pragma unroll
    for (int mb = 0; mb < 2; ++mb)
#pragma unroll
        for (int nb = 0; nb < 4; ++nb)
#pragma unroll
            for (int i = 0; i < 4; ++i) { gacc[mb][nb][i] = 0.f; uacc[mb][nb][i] = 0.f; }

    const int NST = DHID / KS;   // 32

    auto issue = [&](int s) {
        uint32_t st = smA + (s & (NBUF - 1)) * STAGE_B;
        int k0 = s * KS;
        CP16(st + G1_A + adst,      axp + k0,     asz);
        CP16(st + G1_A + adst + 16, axp + k0 + 8, asz);
        CP16(st + G1_G + adst,      bg_src + k0,     16u);
        CP16(st + G1_G + adst + 16, bg_src + k0 + 8, 16u);
        CP16(st + G1_U + adst,      bu_src + k0,     16u);
        CP16(st + G1_U + adst + 16, bu_src + k0 + 8, 16u);
    };

    issue(0); CP_COMMIT();
    issue(1); CP_COMMIT();
    issue(2); CP_COMMIT();

    for (int s = 0; s < NST; ++s) {
        CP_WAIT(2);
        __syncthreads();
        uint32_t st = smA + (s & (NBUF - 1)) * STAGE_B;
#pragma unroll
        for (int kk = 0; kk < 4; ++kk) {
            int kofs = kk * 16;
            uint32_t ah[2][4];
#pragma unroll
            for (int mb = 0; mb < 2; ++mb) {
                uint32_t ao = ((wm + mb * 16 + arl) * AST + kofs + acl) * 2;
                LDSM4(ah[mb][0], ah[mb][1], ah[mb][2], ah[mb][3], st + G1_A + ao);
            }
            uint32_t bg[2][4], bu[2][4];
#pragma unroll
            for (int p = 0; p < 2; ++p) {
                uint32_t bo = ((wn + p * 16 + bnl) * AST + kofs + bkl) * 2;
                LDSM4(bg[p][0], bg[p][1], bg[p][2], bg[p][3], st + G1_G + bo);
                LDSM4(bu[p][0], bu[p][1], bu[p][2], bu[p][3], st + G1_U + bo);
            }
#pragma unroll
            for (int mb = 0; mb < 2; ++mb)
#pragma unroll
                for (int nb = 0; nb < 4; ++nb) {
                    int p = nb >> 1, o = (nb & 1) * 2;
                    MMA(gacc[mb][nb], ah[mb], bg[p][o], bg[p][o + 1]);
                    MMA(uacc[mb][nb], ah[mb], bu[p][o], bu[p][o + 1]);
                }
        }
        if (s + 3 < NST) issue(s + 3);
        CP_COMMIT();
    }

    // epilogue: h = silu(g)*u -> fp16
#pragma unroll
    for (int mb = 0; mb < 2; ++mb) {
#pragma unroll
        for (int half = 0; half < 2; ++half) {
            int m = m0 + wm + mb * 16 + (lane >> 2) + half * 8;
            if (m < cnt) {
                __half* hh = g_h + (size_t)(base + m) * INTER + n0;
#pragma unroll
                for (int nb = 0; nb < 4; ++nb) {
                    int c = wn + nb * 8 + (lane & 3) * 2;
                    float g0 = gacc[mb][nb][half * 2],     g1 = gacc[mb][nb][half * 2 + 1];
                    float u0 = uacc[mb][nb][half * 2],     u1 = uacc[mb][nb][half * 2 + 1];
                    float h0 = silu(g0) * u0, h1 = silu(g1) * u1;
                    *(uint32_t*)(hh + c) = h2u(__float2half_rn(h0), __float2half_rn(h1));
                }
            }
        }
    }
}

// ---------------------------------------------------------------------------
// GEMM2: CTA 128(m) x 256(n), K=1408, KS=64. 16 warps (2m x 8n),
// warp tile 64x32. fp16 stores to g_y.
// ---------------------------------------------------------------------------
__global__ __launch_bounds__(512, 1) void gemm2_mma(void) {
    int e   = blockIdx.z;
    int cnt = g_cnt[e];
    int m0  = blockIdx.y * 128;
    if (m0 >= cnt) return;
    int n0   = blockIdx.x * 256;
    int base = g_off[e];

    extern __shared__ char dynsm[];
    uint32_t raw = smem_u32(dynsm);
    uint32_t smA = (raw + 127u) & ~127u;

    int tid = threadIdx.x, wid = tid >> 5, lane = tid & 31;

    // producers: A 128 rows, 4 thr/row, 2 chunks; B 256 rows, 2 thr/row, 4 chunks
    int arow = tid >> 2;
    int aco  = (tid & 3) * 16;
    bool avalid = (m0 + arow < cnt);
    uint32_t asz = avalid ? 16u : 0u;
    const __half* ahp = g_h + (size_t)(base + (avalid ? m0 + arow : 0)) * INTER + aco;
    uint32_t adst = arow * (AST * 2) + aco * 2;

    int brow = tid >> 1;
    int bco  = (tid & 1) * 32;
    const __half* bp = g_wdT + ((size_t)e * DHID + n0 + brow) * INTER + bco;
    uint32_t bdst = brow * (AST * 2) + bco * 2;

    // consumers: warp (2m x 8n), tile 64x32
    int wm = (wid >> 3) * 64;
    int wn = (wid & 7) * 32;
    int arl = lane & 15, acl = (lane >> 4) * 8;
    int bnl = (lane & 7) + ((lane >> 4) << 3);
    int bkl = ((lane >> 3) & 1) * 8;

    float acc[4][4][4];
#pragma unroll
    for (int mb = 0; mb < 4; ++mb)
#pragma unroll
        for (int nb = 0; nb < 4; ++nb)
#pragma unroll
            for (int i = 0; i < 4; ++i) acc[mb][nb][i] = 0.f;

    const int NST = INTER / KS;  // 22

    auto issue = [&](int s) {
        uint32_t st = smA + (s & (NBUF - 1)) * STAGE_B;
        int k0 = s * KS;
        CP16(st + G2_A + adst,      ahp + k0,     asz);
        CP16(st + G2_A + adst + 16, ahp + k0 + 8, asz);
        CP16(st + G2_B + bdst,      bp + k0,      16u);
        CP16(st + G2_B + bdst + 16, bp + k0 + 8,  16u);
        CP16(st + G2_B + bdst + 32, bp + k0 + 16, 16u);
        CP16(st + G2_B + bdst + 48, bp + k0 + 24, 16u);
    };

    issue(0); CP_COMMIT();
    issue(1); CP_COMMIT();
    issue(2); CP_COMMIT();

    for (int s = 0; s < NST; ++s) {
        CP_WAIT(2);
        __syncthreads();
        uint32_t st = smA + (s & (NBUF - 1)) * STAGE_B;
#pragma unroll
        for (int kk = 0; kk < 4; ++kk) {
            int kofs = kk * 16;
            uint32_t ah[4][4];
#pragma unroll
            for (int mb = 0; mb < 4; ++mb) {
                uint32_t ao = ((wm + mb * 16 + arl) * AST + kofs + acl) * 2;
                LDSM4(ah[mb][0], ah[mb][1], ah[mb][2], ah[mb][3], st + G2_A + ao);
            }
            uint32_t bh[2][4];
#pragma unroll
            for (int p = 0; p < 2; ++p) {
                uint32_t bo = ((wn + p * 16 + bnl) * AST + kofs + bkl) * 2;
                LDSM4(bh[p][0], bh[p][1], bh[p][2], bh[p][3], st + G2_B + bo);
            }
#pragma unroll
            for (int mb = 0; mb < 4; ++mb)
#pragma unroll
                for (int nb = 0; nb < 4; ++nb) {
                    int p = nb >> 1, o = (nb & 1) * 2;
                    MMA(acc[mb][nb], ah[mb], bh[p][o], bh[p][o + 1]);
                }
        }
        if (s + 3 < NST) issue(s + 3);
        CP_COMMIT();
    }

    // epilogue: fp16 stores to g_y
#pragma unroll
    for (int mb = 0; mb < 4; ++mb) {
#pragma unroll
        for (int half = 0; half < 2; ++half) {
            int m = m0 + wm + mb * 16 + (lane >> 2) + half * 8;
            if (m < cnt) {
                __half* yrow = g_y + (size_t)(base + m) * DHID + n0;
#pragma unroll
                for (int nb = 0; nb < 4; ++nb) {
                    int c = wn + nb * 8 + (lane & 3) * 2;
                    *(uint32_t*)(yrow + c) = h2u(
                        __float2half_rn(acc[mb][nb][half * 2]),
                        __float2half_rn(acc[mb][nb][half * 2 + 1]));
                }
            }
        }
    }
}

// ---------------------------------------------------------------------------
// Combine: out[t] = w0 * y[slot0] + w1 * y[slot1]   (y fp16)
// ---------------------------------------------------------------------------
__global__ __launch_bounds__(256) void combine_kernel(float* __restrict__ out) {
    int t = blockIdx.x;
    int e0 = g_s_e[t][0], e1 = g_s_e[t][1];
    size_t s0 = (size_t)(g_off[e0] + g_s_i[t][0]) * DHID;
    size_t s1 = (size_t)(g_off[e1] + g_s_i[t][1]) * DHID;
    float w0 = g_s_w[t][0], w1 = g_s_w[t][1];
    size_t ob = (size_t)t * DHID;
#pragma unroll
    for (int r = 0; r < 2; ++r) {
        int c = (threadIdx.x + r * 256) * 4;
        uint2 au = *(const uint2*)(g_y + s0 + c);
        uint2 bu = *(const uint2*)(g_y + s1 + c);
        float2 a0 = __half22float2(*(__half2*)&au.x);
        float2 a1 = __half22float2(*(__half2*)&au.y);
        float2 b0 = __half22float2(*(__half2*)&bu.x);
        float2 b1 = __half22float2(*(__half2*)&bu.y);
        float4 o;
        o.x = w0 * a0.x + w1 * b0.x;
        o.y = w0 * a0.y + w1 * b0.y;
        o.z = w0 * a1.x + w1 * b1.x;
        o.w = w0 * a1.y + w1 * b1.y;
        *(float4*)(out + ob + c) = o;
    }
}

// ---------------------------------------------------------------------------
extern "C" void kernel_launch(void* const* d_in, const int* in_sizes, int n_in,
                              void* d_out, int out_size) {
    const float* x  = (const float*)d_in[0];
    const float* gw = (const float*)d_in[1];
    const float* wg = (const float*)d_in[2];
    const float* wu = (const float*)d_in[3];
    const float* wd = (const float*)d_in[4];
    float* out = (float*)d_out;

    cudaFuncSetAttribute(gemm1_mma, cudaFuncAttributeMaxDynamicSharedMemorySize, SMEM_DYN);
    cudaFuncSetAttribute(gemm2_mma, cudaFuncAttributeMaxDynamicSharedMemorySize, SMEM_DYN);

    zero16_kernel<<<1, 32>>>();
    router_kernel<<<NTOK / 8, 256>>>(x, gw);
    offsets_kernel<<<1, 32>>>();
    convert_x_kernel<<<(NTOK * DHID / 4 + 255) / 256, 256>>>(x);
    transpose_h_kernel<<<dim3(INTER / 32, DHID / 32, NEXP), dim3(32, 8)>>>(wg, 0, DHID, INTER);
    transpose_h_kernel<<<dim3(INTER / 32, DHID / 32, NEXP), dim3(32, 8)>>>(wu, 1, DHID, INTER);
    transpose_h_kernel<<<dim3(DHID / 32, INTER / 32, NEXP), dim3(32, 8)>>>(wd, 2, INTER, DHID);
    gemm1_mma<<<dim3(INTER / 128, NTOK / 128, NEXP), 512, SMEM_DYN>>>();
    gemm2_mma<<<dim3(DHID / 256, NTOK / 128, NEXP), 512, SMEM_DYN>>>();
    combine_kernel<<<NTOK, 256>>>(out);
}